// round 15
// baseline (speedup 1.0000x reference)
#include <cuda_runtime.h>
#include <cuda_fp16.h>
#include <cstdint>

// Modulated deformable conv 3x3, in_ch=out_ch=1, stride=1, pad=1, dil=1.
// H=W=512, B<=8. R15: R13 main kernel (fp16x2 paired-depth gathers, plain
// stores) + PDL overlap: dcn launches programmatically-dependent on prep,
// issues its offset/mask cp.async prologue BEFORE cudaGridDependencySynchronize,
// so prep's tail hides under dcn's streaming prologue.

#define Hc 512
#define Wc 512
#define HWc (Hc * Wc)
#define TW 516                    // padded tile entries per row (513 used)
#define THWc (Hc * TW)
#define NS 3                      // pipeline stages
#define SLAB_FLOATS 192           // dy[64] dx[64] m[64] per warp per stage
#define STAGE_BYTES (8 * SLAB_FLOATS * 4)

__device__ __align__(16) __half2 g_pair[8 * THWc];   // 8.5 MB scratch

__device__ __forceinline__ uint32_t smem_u32(const void* p) {
    uint32_t a;
    asm("{ .reg .u64 t; cvta.to.shared.u64 t, %1; cvt.u32.u64 %0, t; }"
        : "=r"(a) : "l"(p));
    return a;
}

#define CP_ASYNC_16(dst, src) \
    asm volatile("cp.async.cg.shared.global [%0], [%1], 16;" \
                 :: "r"(dst), "l"(src) : "memory")
#define CP_COMMIT() asm volatile("cp.async.commit_group;" ::: "memory")
#define CP_WAIT(n)  asm volatile("cp.async.wait_group %0;" :: "n"(n) : "memory")

// ---- kernel 1: build fp16 paired depth tile -----------------------------
// Block = one image row, 128 threads. Thread t covers entries [4t, 4t+4):
// one float4 load, one uint4 store. Entry e = {fp16(d[e-1]|0), fp16(d[e]|0)}.
__global__ __launch_bounds__(128)
void prep_kernel(const float* __restrict__ depth)
{
    int t = threadIdx.x;               // 0..127
    int y = blockIdx.x & 511;
    int b = blockIdx.x >> 9;
    const float* row = depth + (size_t)b * HWc + (y << 9);

    int e0 = t << 2;                   // 0,4,...,508
    float4 v = *(const float4*)(row + e0);            // d[e0..e0+3]
    float lm = (e0 > 0) ? __ldg(row + e0 - 1) : 0.0f; // d[e0-1]

    __half2 h0 = __floats2half2_rn(lm,  v.x);
    __half2 h1 = __floats2half2_rn(v.x, v.y);
    __half2 h2 = __floats2half2_rn(v.y, v.z);
    __half2 h3 = __floats2half2_rn(v.z, v.w);

    __half2* dst = g_pair + (size_t)b * THWc + y * TW + e0;
    uint4 pack;
    pack.x = *(uint32_t*)&h0;
    pack.y = *(uint32_t*)&h1;
    pack.z = *(uint32_t*)&h2;
    pack.w = *(uint32_t*)&h3;
    *(uint4*)dst = pack;

    if (t == 127) {                    // entry 512 = {d[511], 0}
        dst[4] = __floats2half2_rn(v.w, 0.0f);
    }

#if __CUDA_ARCH__ >= 900
    cudaTriggerProgrammaticLaunchCompletion();
#endif
}

// ---- bilinear from fp16 paired tile: 2 predicated 4B LDGs ---------------
__device__ __forceinline__ float bilin_pair(const __half2* __restrict__ tb,
                                            float y, float x) {
    float y0f = floorf(y);
    float x0f = floorf(x);
    float wy = y - y0f;
    float wx = x - x0f;
    int y0  = (int)y0f;
    int txx = (int)x0f + 1;                 // tile x index, valid [0,512]
    bool vx  = (unsigned)txx <= 512u;
    bool vy0 = vx && ((unsigned)y0       < (unsigned)Hc);
    bool vy1 = vx && ((unsigned)(y0 + 1) < (unsigned)Hc);
    const __half2* p = tb + y0 * TW + txx;
    __half2 z = __half2half2(__float2half(0.0f));
    __half2 a = vy0 ? __ldg(p)      : z;
    __half2 c = vy1 ? __ldg(p + TW) : z;
    float2 af = __half22float2(a);
    float2 cf = __half22float2(c);
    float top = fmaf(wx, af.y - af.x, af.x);
    float bot = fmaf(wx, cf.y - cf.x, cf.x);
    return fmaf(wy, bot - top, top);
}

// ---- kernel 2: main DCN --------------------------------------------------
__global__ __launch_bounds__(256, 8)
void dcn_kernel(const float* __restrict__ mask,
                const float* __restrict__ off,
                const float* __restrict__ w9,
                const float* __restrict__ bias,
                float* __restrict__ out,
                int B)
{
    __shared__ __align__(16) float slab[NS][8][SLAB_FLOATS];

    int tid  = threadIdx.x;
    int lane = tid & 31;
    int wrp  = tid >> 5;
    int bid  = blockIdx.x;
    int b    = bid >> 9;          // 512 blocks per image
    int rem  = bid & 511;
    int ys   = rem >> 1;          // 256 y-strips of 2 rows
    int xs   = rem & 1;           // 2 x-strips of 256 px
    int y0   = ys << 1;
    int xw   = (xs << 8) + (wrp << 5);
    int x    = xw + lane;

    const __half2* tb  = g_pair + (size_t)b * THWc;
    const float* obase = off  + (size_t)b * 18 * HWc + (y0 << 9) + xw;
    const float* mbase = mask + (size_t)b * 9  * HWc + (y0 << 9) + xw;

    // Cooperative copy mapping (see R8-R10)
    int arr  = lane >> 4;
    int cc   = lane & 15;
    int coff = ((cc >> 3) << 9) + ((cc & 7) << 2);
    int moff = ((lane >> 3) << 9) + ((lane & 7) << 2);

    uint32_t warp_base = smem_u32(&slab[0][wrp][0]);
    uint32_t adst0 = warp_base + (uint32_t)lane * 16;
    uint32_t bdst0 = warp_base + 512 + (uint32_t)lane * 16;

    // Streaming prologue — reads ONLY offset/mask, independent of prep.
    // Runs while prep's tail is still in flight (PDL overlap).
    #pragma unroll
    for (int t = 0; t < NS; t++) {
        CP_ASYNC_16(adst0 + t * STAGE_BYTES, obase + (size_t)(2 * t + arr) * HWc + coff);
        if (lane < 16)
            CP_ASYNC_16(bdst0 + t * STAGE_BYTES, mbase + (size_t)t * HWc + moff);
        CP_COMMIT();
    }

#if __CUDA_ARCH__ >= 900
    // Gate only the gather phase on prep completion.
    cudaGridDependencySynchronize();
#endif

    float acc0 = 0.0f, acc1 = 0.0f;
    float xf = (float)x;

    #pragma unroll
    for (int t = 0; t < 9; t++) {
        const int s = t % NS;

        CP_WAIT(NS - 1);
        __syncwarp();

        const float* f = &slab[s][wrp][0];
        float dy0 = f[lane],       dy1 = f[32 + lane];
        float dx0 = f[64 + lane],  dx1 = f[96 + lane];
        float m0  = f[128 + lane], m1  = f[160 + lane];

        int tn = t + NS;
        if (tn < 9) {
            CP_ASYNC_16(adst0 + s * STAGE_BYTES, obase + (size_t)(2 * tn + arr) * HWc + coff);
            if (lane < 16)
                CP_ASYNC_16(bdst0 + s * STAGE_BYTES, mbase + (size_t)tn * HWc + moff);
        }
        CP_COMMIT();

        float wt = __ldg(w9 + t);
        float ybase = (float)(y0 - 1 + t / 3);
        float xtap  = xf + (float)(t % 3 - 1);

        float sv;
        sv = bilin_pair(tb, ybase + 0.0f + dy0, xtap + dx0);
        acc0 = fmaf(sv, m0 * wt, acc0);
        sv = bilin_pair(tb, ybase + 1.0f + dy1, xtap + dx1);
        acc1 = fmaf(sv, m1 * wt, acc1);
    }

    float bv = __ldg(bias);
    float* optr = out + (size_t)b * HWc + (y0 << 9) + x;
    optr[0]  = acc0 + bv;                 // plain stores (stcs regressed)
    optr[Wc] = acc1 + bv;
}

extern "C" void kernel_launch(void* const* d_in, const int* in_sizes, int n_in,
                              void* d_out, int out_size)
{
    const float* depth = (const float*)d_in[0];
    const float* mask  = (const float*)d_in[1];
    const float* off   = (const float*)d_in[2];
    const float* w9    = (const float*)d_in[3];
    const float* bias  = (const float*)d_in[4];
    float* out = (float*)d_out;

    int B = in_sizes[0] / HWc;

    prep_kernel<<<B * 512, 128>>>(depth);

    // PDL launch: dcn may begin (and run its streaming prologue) while prep
    // finishes; the grid-dependency sync inside gates only the gathers.
    cudaLaunchConfig_t cfg = {};
    cfg.gridDim  = dim3(B * 512, 1, 1);
    cfg.blockDim = dim3(256, 1, 1);
    cfg.dynamicSmemBytes = 0;
    cfg.stream = 0;
    cudaLaunchAttribute attrs[1];
    attrs[0].id = cudaLaunchAttributeProgrammaticStreamSerialization;
    attrs[0].val.programmaticStreamSerializationAllowed = 1;
    cfg.attrs = attrs;
    cfg.numAttrs = 1;
    cudaLaunchKernelEx(&cfg, dcn_kernel, mask, off, w9, bias, out, B);
}

// round 16
// speedup vs baseline: 1.0118x; 1.0118x over previous
#include <cuda_runtime.h>
#include <cuda_fp16.h>
#include <cstdint>

// Modulated deformable conv 3x3, in_ch=out_ch=1, stride=1, pad=1, dil=1.
// H=W=512, B<=8. R16: single PERSISTENT kernel. Phase 1 builds the fp16x2
// paired-depth tile (strided over rows), then a software grid barrier
// (cumulative-epoch counter, replay-safe, deadlock-free because grid ==
// co-resident CTA count from the occupancy API), then phase 2 runs the R13
// dcn body (strided over tiles). Removes the inter-kernel wave-drain gap
// and leaves the tile L2-hot for the gathers.

#define Hc 512
#define Wc 512
#define HWc (Hc * Wc)
#define TW 516                    // padded tile entries per row (513 used)
#define THWc (Hc * TW)
#define NS 3                      // pipeline stages
#define SLAB_FLOATS 192           // dy[64] dx[64] m[64] per warp per stage
#define STAGE_BYTES (8 * SLAB_FLOATS * 4)

__device__ __align__(16) __half2 g_pair[8 * THWc];     // 8.5 MB scratch
__device__ unsigned long long g_epoch = 0ULL;          // cumulative barrier

__device__ __forceinline__ uint32_t smem_u32(const void* p) {
    uint32_t a;
    asm("{ .reg .u64 t; cvta.to.shared.u64 t, %1; cvt.u32.u64 %0, t; }"
        : "=r"(a) : "l"(p));
    return a;
}

#define CP_ASYNC_16(dst, src) \
    asm volatile("cp.async.cg.shared.global [%0], [%1], 16;" \
                 :: "r"(dst), "l"(src) : "memory")
#define CP_COMMIT() asm volatile("cp.async.commit_group;" ::: "memory")
#define CP_WAIT(n)  asm volatile("cp.async.wait_group %0;" :: "n"(n) : "memory")

// ---- bilinear from fp16 paired tile: 2 predicated 4B LDGs ---------------
__device__ __forceinline__ float bilin_pair(const __half2* __restrict__ tb,
                                            float y, float x) {
    float y0f = floorf(y);
    float x0f = floorf(x);
    float wy = y - y0f;
    float wx = x - x0f;
    int y0  = (int)y0f;
    int txx = (int)x0f + 1;                 // tile x index, valid [0,512]
    bool vx  = (unsigned)txx <= 512u;
    bool vy0 = vx && ((unsigned)y0       < (unsigned)Hc);
    bool vy1 = vx && ((unsigned)(y0 + 1) < (unsigned)Hc);
    const __half2* p = tb + y0 * TW + txx;
    __half2 z = __half2half2(__float2half(0.0f));
    __half2 a = vy0 ? __ldg(p)      : z;
    __half2 c = vy1 ? __ldg(p + TW) : z;
    float2 af = __half22float2(a);
    float2 cf = __half22float2(c);
    float top = fmaf(wx, af.y - af.x, af.x);
    float bot = fmaf(wx, cf.y - cf.x, cf.x);
    return fmaf(wy, bot - top, top);
}

__global__ __launch_bounds__(256, 8)
void dcn_kernel(const float* __restrict__ depth,
                const float* __restrict__ mask,
                const float* __restrict__ off,
                const float* __restrict__ w9,
                const float* __restrict__ bias,
                float* __restrict__ out,
                int B)
{
    __shared__ __align__(16) float slab[NS][8][SLAB_FLOATS];
    __shared__ int s_release;

    int tid  = threadIdx.x;
    int lane = tid & 31;
    int wrp  = tid >> 5;
    int G    = gridDim.x;

    // ---------------- Phase 1: build paired fp16 tile --------------------
    // 256 threads handle 2 rows per iteration (t = tid&127 within a row).
    {
        int nrow2 = B * 256;                  // row pairs
        int t  = tid & 127;
        int rh = tid >> 7;                    // 0/1: which row of the pair
        for (int rr = blockIdx.x; rr < nrow2; rr += G) {
            int row_idx = (rr << 1) + rh;     // 0 .. B*512-1
            int y = row_idx & 511;
            int b = row_idx >> 9;
            const float* row = depth + (size_t)b * HWc + (y << 9);

            int e0 = t << 2;                  // 0,4,...,508
            float4 v = *(const float4*)(row + e0);
            float lm = (e0 > 0) ? __ldg(row + e0 - 1) : 0.0f;

            __half2 h0 = __floats2half2_rn(lm,  v.x);
            __half2 h1 = __floats2half2_rn(v.x, v.y);
            __half2 h2 = __floats2half2_rn(v.y, v.z);
            __half2 h3 = __floats2half2_rn(v.z, v.w);

            __half2* dst = g_pair + (size_t)b * THWc + y * TW + e0;
            uint4 pack;
            pack.x = *(uint32_t*)&h0;
            pack.y = *(uint32_t*)&h1;
            pack.z = *(uint32_t*)&h2;
            pack.w = *(uint32_t*)&h3;
            *(uint4*)dst = pack;
            if (t == 127)                     // entry 512 = {d[511], 0}
                dst[4] = __floats2half2_rn(v.w, 0.0f);
        }
    }

    // ---------------- Grid barrier (cumulative epoch, replay-safe) -------
    __syncthreads();
    if (tid == 0) {
        __threadfence();                                  // release my writes
        unsigned long long my = atomicAdd(&g_epoch, 1ULL) + 1ULL;
        unsigned long long target = ((my + (unsigned long long)G - 1ULL)
                                     / (unsigned long long)G)
                                    * (unsigned long long)G;
        while (true) {
            unsigned long long cur;
            asm volatile("ld.global.acquire.gpu.u64 %0, [%1];"
                         : "=l"(cur) : "l"(&g_epoch) : "memory");
            if (cur >= target) break;
            __nanosleep(64);
        }
        s_release = 1;
    }
    __syncthreads();                                      // all threads gated
    (void)s_release;

    // ---------------- Phase 2: DCN tiles ---------------------------------
    for (int bid = blockIdx.x; bid < B * 512; bid += G) {
        int b    = bid >> 9;
        int rem  = bid & 511;
        int ys   = rem >> 1;
        int xs   = rem & 1;
        int y0   = ys << 1;
        int xw   = (xs << 8) + (wrp << 5);
        int x    = xw + lane;

        const __half2* tb  = g_pair + (size_t)b * THWc;
        const float* obase = off  + (size_t)b * 18 * HWc + (y0 << 9) + xw;
        const float* mbase = mask + (size_t)b * 9  * HWc + (y0 << 9) + xw;

        int arr  = lane >> 4;
        int cc   = lane & 15;
        int coff = ((cc >> 3) << 9) + ((cc & 7) << 2);
        int moff = ((lane >> 3) << 9) + ((lane & 7) << 2);

        uint32_t warp_base = smem_u32(&slab[0][wrp][0]);
        uint32_t adst0 = warp_base + (uint32_t)lane * 16;
        uint32_t bdst0 = warp_base + 512 + (uint32_t)lane * 16;

        #pragma unroll
        for (int t = 0; t < NS; t++) {
            CP_ASYNC_16(adst0 + t * STAGE_BYTES, obase + (size_t)(2 * t + arr) * HWc + coff);
            if (lane < 16)
                CP_ASYNC_16(bdst0 + t * STAGE_BYTES, mbase + (size_t)t * HWc + moff);
            CP_COMMIT();
        }

        float acc0 = 0.0f, acc1 = 0.0f;
        float xf = (float)x;

        #pragma unroll
        for (int t = 0; t < 9; t++) {
            const int s = t % NS;

            CP_WAIT(NS - 1);
            __syncwarp();

            const float* f = &slab[s][wrp][0];
            float dy0 = f[lane],       dy1 = f[32 + lane];
            float dx0 = f[64 + lane],  dx1 = f[96 + lane];
            float m0  = f[128 + lane], m1  = f[160 + lane];

            int tn = t + NS;
            if (tn < 9) {
                CP_ASYNC_16(adst0 + s * STAGE_BYTES, obase + (size_t)(2 * tn + arr) * HWc + coff);
                if (lane < 16)
                    CP_ASYNC_16(bdst0 + s * STAGE_BYTES, mbase + (size_t)tn * HWc + moff);
            }
            CP_COMMIT();

            float wt = __ldg(w9 + t);
            float ybase = (float)(y0 - 1 + t / 3);
            float xtap  = xf + (float)(t % 3 - 1);

            float sv;
            sv = bilin_pair(tb, ybase + 0.0f + dy0, xtap + dx0);
            acc0 = fmaf(sv, m0 * wt, acc0);
            sv = bilin_pair(tb, ybase + 1.0f + dy1, xtap + dx1);
            acc1 = fmaf(sv, m1 * wt, acc1);
        }

        float bv = __ldg(bias);
        float* optr = out + (size_t)b * HWc + (y0 << 9) + x;
        optr[0]  = acc0 + bv;
        optr[Wc] = acc1 + bv;
        // drain this tile's outstanding groups before reusing the slab
        CP_WAIT(0);
        __syncthreads();
    }
}

extern "C" void kernel_launch(void* const* d_in, const int* in_sizes, int n_in,
                              void* d_out, int out_size)
{
    const float* depth = (const float*)d_in[0];
    const float* mask  = (const float*)d_in[1];
    const float* off   = (const float*)d_in[2];
    const float* w9    = (const float*)d_in[3];
    const float* bias  = (const float*)d_in[4];
    float* out = (float*)d_out;

    int B = in_sizes[0] / HWc;

    // Grid = guaranteed co-resident CTA count (deadlock-free barrier).
    int dev = 0;
    cudaGetDevice(&dev);
    int sms = 0;
    cudaDeviceGetAttribute(&sms, cudaDevAttrMultiProcessorCount, dev);
    int occ = 0;
    cudaOccupancyMaxActiveBlocksPerMultiprocessor(&occ, dcn_kernel, 256, 0);
    if (occ < 1) occ = 1;
    long long want = (long long)sms * occ;
    long long work = (long long)B * 512;
    int grid = (int)(want < work ? want : work);

    dcn_kernel<<<grid, 256>>>(depth, mask, off, w9, bias, out, B);
}